// round 1
// baseline (speedup 1.0000x reference)
#include <cuda_runtime.h>

#define EPSF 1e-5f

namespace {
constexpr int K = 4, B = 1024, C = 128, T = 64, D = 64;
constexpr int THREADS = 256;
constexpr int CTXP = 65;        // ctx row pitch (pad vs 64 to kill bank conflicts)
constexpr int WP   = 65;        // transposed-weight row pitch
constexpr int AGGP = 4097;      // per-head stride in bufA (pad vs 4096)

// shared memory layout (float offsets)
constexpr int OFF_CTX = 0;                    // 256 rows * 65  = 16640
constexpr int OFF_W   = OFF_CTX + 256 * CTXP; // 4 mats * 64*65 = 16640
constexpr int OFF_A   = OFF_W + 4 * 64 * WP;  // 16640 (QK/AGG [h][r][t], OBUF, feats staging)
constexpr int OFF_B   = OFF_A + 16640;        // 4096  (QP / OA [r][e])
constexpr int OFF_AB  = OFF_B + 4096;         // 1024  (softmax weights [r][h][k'])
constexpr int SMEM_FLOATS = OFF_AB + 1024;    // 55040 floats = 215 KB
}

__device__ __forceinline__ float warp_sum(float v) {
#pragma unroll
    for (int o = 16; o; o >>= 1) v += __shfl_xor_sync(0xffffffffu, v, o);
    return v;
}

__global__ __launch_bounds__(THREADS, 1)
void cma_fused(const float* __restrict__ feats, const float* __restrict__ proj_w,
               const float* __restrict__ proj_b, const float* __restrict__ wq,
               const float* __restrict__ wk, const float* __restrict__ wv,
               const float* __restrict__ bq, const float* __restrict__ bk,
               const float* __restrict__ bv, const float* __restrict__ wo,
               const float* __restrict__ bo, const float* __restrict__ ng,
               const float* __restrict__ nb, const float* __restrict__ tfw,
               const float* __restrict__ fg, const float* __restrict__ fb,
               float* __restrict__ out)
{
    (void)bk;  // provably cancels in the k'-softmax (constant per (n,h))

    extern __shared__ float sm[];
    float* sctx = sm + OFF_CTX;
    float* swgt = sm + OFF_W;
    float* bufA = sm + OFF_A;
    float* bufB = sm + OFF_B;
    float* abuf = sm + OFF_AB;

    const int b    = blockIdx.x;
    const int tid  = threadIdx.x;
    const int lane = tid & 31;
    const int warp = tid >> 5;
    const int tr   = tid >> 4;   // 0..15  (row-group)
    const int tc   = tid & 15;   // 0..15  (col-group)
    const int r0   = tr * 4;
    const int c0   = tc * 4;

    // combiner weights: softmax(tfw), K=4
    float wgt[4];
    {
        float t0 = __ldg(tfw + 0), t1 = __ldg(tfw + 1), t2 = __ldg(tfw + 2), t3 = __ldg(tfw + 3);
        float tm = fmaxf(fmaxf(t0, t1), fmaxf(t2, t3));
        float e0 = __expf(t0 - tm), e1 = __expf(t1 - tm), e2 = __expf(t2 - tm), e3 = __expf(t3 - tm);
        float inv = 1.f / (e0 + e1 + e2 + e3);
        wgt[0] = e0 * inv; wgt[1] = e1 * inv; wgt[2] = e2 * inv; wgt[3] = e3 * inv;
    }

    // ================= Phase 1: proj -> sctx[(k*64+d)*CTXP + t] =================
    {
        float* sfeat = bufA;   // [c][t], 128*64
        float* spw   = swgt;   // [c*WP + d], transposed proj_w
        for (int k = 0; k < 4; k++) {
            const float4* fg4 = reinterpret_cast<const float4*>(feats + (size_t)(k * B + b) * (C * T));
            float4* sf4 = reinterpret_cast<float4*>(sfeat);
#pragma unroll
            for (int idx = tid; idx < C * T / 4; idx += THREADS) sf4[idx] = fg4[idx];
            const float* pwg = proj_w + k * (D * C);
#pragma unroll
            for (int idx = tid; idx < D * C; idx += THREADS) {
                int d = idx >> 7, c = idx & 127;
                spw[c * WP + d] = pwg[idx];
            }
            __syncthreads();

            float acc[4][4] = {};
            const float4* sfv = reinterpret_cast<const float4*>(sfeat);
#pragma unroll 8
            for (int c = 0; c < C; c++) {
                float4 f = sfv[c * 16 + tc];
#pragma unroll
                for (int j = 0; j < 4; j++) {
                    float w = spw[c * WP + r0 + j];
                    acc[j][0] += w * f.x; acc[j][1] += w * f.y;
                    acc[j][2] += w * f.z; acc[j][3] += w * f.w;
                }
            }
#pragma unroll
            for (int j = 0; j < 4; j++) {
                float pb = __ldg(proj_b + k * D + r0 + j);
                float* dst = sctx + (k * 64 + r0 + j) * CTXP + c0;
                dst[0] = acc[j][0] + pb; dst[1] = acc[j][1] + pb;
                dst[2] = acc[j][2] + pb; dst[3] = acc[j][3] + pb;
            }
            __syncthreads();
        }
    }

    // ================= Phase 2: attention for each model i =================
    for (int i = 0; i < 4; i++) {
        // stage transposed weights: s[t*WP+e] = w[e*64+t]
        {
            const float* gq = wq + i * 4096; const float* gk = wk + i * 4096;
            const float* gv = wv + i * 4096; const float* go = wo + i * 4096;
#pragma unroll
            for (int idx = tid; idx < 4096; idx += THREADS) {
                int e = idx >> 6, t = idx & 63;
                swgt[0 * 64 * WP + t * WP + e] = gq[idx];
                swgt[1 * 64 * WP + t * WP + e] = gk[idx];
                swgt[2 * 64 * WP + t * WP + e] = gv[idx];
                swgt[3 * 64 * WP + t * WP + e] = go[idx];
            }
        }
        __syncthreads();
        const float* swq_ = swgt;
        const float* swk_ = swgt + 64 * WP;
        const float* swv_ = swgt + 2 * 64 * WP;
        const float* swo_ = swgt + 3 * 64 * WP;

        int jb_[4], jq_[4];
#pragma unroll
        for (int rr = 0; rr < 4; rr++) {
            int r = r0 + rr;
            jb_[rr] = ((r >> 4) << 6) + ((r & 15) << 2);
            jq_[rr] = jb_[rr] + i;
        }

        // ---- G1: QP[r][e] = bq[e] + q_in[r] @ wq^T  -> bufB ----
        {
            float acc[4][4] = {};
#pragma unroll 8
            for (int t = 0; t < 64; t++) {
                float qv[4];
#pragma unroll
                for (int rr = 0; rr < 4; rr++) qv[rr] = sctx[jq_[rr] * CTXP + t];
#pragma unroll
                for (int j = 0; j < 4; j++) {
                    float w = swq_[t * WP + c0 + j];
                    acc[0][j] += qv[0] * w; acc[1][j] += qv[1] * w;
                    acc[2][j] += qv[2] * w; acc[3][j] += qv[3] * w;
                }
            }
#pragma unroll
            for (int rr = 0; rr < 4; rr++)
#pragma unroll
                for (int j = 0; j < 4; j++)
                    bufB[(r0 + rr) * 64 + c0 + j] = acc[rr][j] + __ldg(bq + i * 64 + c0 + j);
        }
        __syncthreads();

        // ---- G2: QK[h][r][t] = 0.25 * sum_{e in head h} QP[r][e] * wk[e][t] ----
#pragma unroll
        for (int h = 0; h < 4; h++) {
            float acc[4][4] = {};
#pragma unroll
            for (int ee = 0; ee < 16; ee++) {
                int e = h * 16 + ee;
                float qp[4];
#pragma unroll
                for (int rr = 0; rr < 4; rr++) qp[rr] = bufB[(r0 + rr) * 64 + e];
#pragma unroll
                for (int j = 0; j < 4; j++) {
                    float w = swk_[(c0 + j) * WP + e];
                    acc[0][j] += qp[0] * w; acc[1][j] += qp[1] * w;
                    acc[2][j] += qp[2] * w; acc[3][j] += qp[3] * w;
                }
            }
#pragma unroll
            for (int rr = 0; rr < 4; rr++)
#pragma unroll
                for (int j = 0; j < 4; j++)
                    bufA[h * AGGP + (r0 + rr) * 64 + c0 + j] = acc[rr][j] * 0.25f;
        }
        __syncthreads();

        // ---- G3a: scores + softmax over k' (4) -> abuf[r*16 + h*4 + kp] ----
#pragma unroll
        for (int p = 0; p < 4; p++) {
            int r   = warp * 8 + p * 2 + (lane >> 4);
            int sub = lane & 15;
            int h   = sub >> 2, kp = sub & 3;
            int j   = ((r >> 4) << 6) + ((r & 15) << 2) + kp;
            const float* qrow = bufA + h * AGGP + r * 64;
            const float* crow = sctx + j * CTXP;
            float s = 0.f;
#pragma unroll 8
            for (int t = 0; t < 64; t++) s += qrow[t] * crow[t];
            float m = fmaxf(s, __shfl_xor_sync(0xffffffffu, s, 1));
            m = fmaxf(m, __shfl_xor_sync(0xffffffffu, m, 2));
            float pe  = __expf(s - m);
            float den = pe + __shfl_xor_sync(0xffffffffu, pe, 1);
            den += __shfl_xor_sync(0xffffffffu, den, 2);
            abuf[r * 16 + sub] = pe / den;
        }
        __syncthreads();

        // ---- G3b: AGG[h][r][t] = sum_kp a[r,h,kp] * ctx[j(r,kp)][t]  (overwrites QK) ----
#pragma unroll
        for (int h = 0; h < 4; h++) {
            float acc[4][4] = {};
#pragma unroll
            for (int kp = 0; kp < 4; kp++) {
#pragma unroll
                for (int rr = 0; rr < 4; rr++) {
                    float a = abuf[(r0 + rr) * 16 + h * 4 + kp];
                    const float* crow = sctx + (jb_[rr] + kp) * CTXP + c0;
                    acc[rr][0] += a * crow[0]; acc[rr][1] += a * crow[1];
                    acc[rr][2] += a * crow[2]; acc[rr][3] += a * crow[3];
                }
            }
#pragma unroll
            for (int rr = 0; rr < 4; rr++)
#pragma unroll
                for (int j = 0; j < 4; j++)
                    bufA[h * AGGP + (r0 + rr) * 64 + c0 + j] = acc[rr][j];
        }
        __syncthreads();

        // ---- G4: OA[r][e] = bv[e] + sum_t AGG[h(e)][r][t] * wv[e][t] -> bufB ----
        {
            int h = c0 >> 4;
            float acc[4][4] = {};
#pragma unroll 8
            for (int t = 0; t < 64; t++) {
                float g[4];
#pragma unroll
                for (int rr = 0; rr < 4; rr++) g[rr] = bufA[h * AGGP + (r0 + rr) * 64 + t];
#pragma unroll
                for (int j = 0; j < 4; j++) {
                    float w = swv_[t * WP + c0 + j];
                    acc[0][j] += g[0] * w; acc[1][j] += g[1] * w;
                    acc[2][j] += g[2] * w; acc[3][j] += g[3] * w;
                }
            }
#pragma unroll
            for (int rr = 0; rr < 4; rr++)
#pragma unroll
                for (int j = 0; j < 4; j++)
                    bufB[(r0 + rr) * 64 + c0 + j] = acc[rr][j] + __ldg(bv + i * 64 + c0 + j);
        }
        __syncthreads();

        // ---- G5: O[r][e'] = bo + OA @ wo^T -> bufA[r*64+e'] ----
        {
            float acc[4][4] = {};
#pragma unroll 8
            for (int e = 0; e < 64; e++) {
                float ov[4];
#pragma unroll
                for (int rr = 0; rr < 4; rr++) ov[rr] = bufB[(r0 + rr) * 64 + e];
#pragma unroll
                for (int j = 0; j < 4; j++) {
                    float w = swo_[e * WP + c0 + j];
                    acc[0][j] += ov[0] * w; acc[1][j] += ov[1] * w;
                    acc[2][j] += ov[2] * w; acc[3][j] += ov[3] * w;
                }
            }
#pragma unroll
            for (int rr = 0; rr < 4; rr++)
#pragma unroll
                for (int j = 0; j < 4; j++)
                    bufA[(r0 + rr) * 64 + c0 + j] = acc[rr][j] + __ldg(bo + i * 64 + c0 + j);
        }
        __syncthreads();

        // ---- LN over 64 (+residual q_in), scale by wgt[i], stage into out ----
#pragma unroll
        for (int p = 0; p < 8; p++) {
            int r   = warp * 8 + p;
            int jqr = ((r >> 4) << 6) + ((r & 15) << 2) + i;
            float x0 = bufA[r * 64 + lane]      + sctx[jqr * CTXP + lane];
            float x1 = bufA[r * 64 + lane + 32] + sctx[jqr * CTXP + lane + 32];
            float mean = warp_sum(x0 + x1) * (1.f / 64.f);
            float d0 = x0 - mean, d1 = x1 - mean;
            float var = warp_sum(d0 * d0 + d1 * d1) * (1.f / 64.f);
            float rs = rsqrtf(var + EPSF);
            float* dst = out + ((size_t)b * 16384 + r * 256 + i * 64);
            dst[lane]      = (d0 * rs * __ldg(ng + i * 64 + lane)      + __ldg(nb + i * 64 + lane))      * wgt[i];
            dst[lane + 32] = (d1 * rs * __ldg(ng + i * 64 + lane + 32) + __ldg(nb + i * 64 + lane + 32)) * wgt[i];
        }
        __syncthreads();
    }

    // ================= Phase 3: final LN over K*D = 256, in-place on out =================
#pragma unroll
    for (int p = 0; p < 8; p++) {
        int r = warp * 8 + p;
        float* row = out + ((size_t)b * 16384 + r * 256);
        float x[8];
        float s = 0.f;
#pragma unroll
        for (int q = 0; q < 8; q++) { x[q] = row[lane + 32 * q]; s += x[q]; }
        float mean = warp_sum(s) * (1.f / 256.f);
        float v = 0.f;
#pragma unroll
        for (int q = 0; q < 8; q++) { x[q] -= mean; v += x[q] * x[q]; }
        float var = warp_sum(v) * (1.f / 256.f);
        float rs = rsqrtf(var + EPSF);
#pragma unroll
        for (int q = 0; q < 8; q++) {
            int jj = lane + 32 * q;
            row[jj] = x[q] * rs * __ldg(fg + jj) + __ldg(fb + jj);
        }
    }
}

extern "C" void kernel_launch(void* const* d_in, const int* in_sizes, int n_in,
                              void* d_out, int out_size) {
    (void)in_sizes; (void)n_in; (void)out_size;
    const float* feats  = (const float*)d_in[0];
    const float* proj_w = (const float*)d_in[1];
    const float* proj_b = (const float*)d_in[2];
    const float* wq     = (const float*)d_in[3];
    const float* wk     = (const float*)d_in[4];
    const float* wv     = (const float*)d_in[5];
    const float* bq     = (const float*)d_in[6];
    const float* bk     = (const float*)d_in[7];
    const float* bv     = (const float*)d_in[8];
    const float* wo     = (const float*)d_in[9];
    const float* bo     = (const float*)d_in[10];
    const float* ng     = (const float*)d_in[11];
    const float* nb     = (const float*)d_in[12];
    const float* tfw    = (const float*)d_in[13];
    const float* fg     = (const float*)d_in[14];
    const float* fb     = (const float*)d_in[15];
    float* out = (float*)d_out;

    size_t smem = SMEM_FLOATS * sizeof(float);
    cudaFuncSetAttribute(cma_fused, cudaFuncAttributeMaxDynamicSharedMemorySize, (int)smem);
    cma_fused<<<B, THREADS, smem>>>(feats, proj_w, proj_b, wq, wk, wv, bq, bk, bv,
                                    wo, bo, ng, nb, tfw, fg, fb, out);
}

// round 2
// speedup vs baseline: 1.0005x; 1.0005x over previous
#include <cuda_runtime.h>

#define EPSF 1e-5f

namespace {
constexpr int K = 4, B = 1024, C = 128, T = 64, D = 64;
constexpr int THREADS = 256;
constexpr int CTXP = 65;        // ctx row pitch (pad vs 64 to kill bank conflicts)
constexpr int WP   = 65;        // transposed-weight row pitch
constexpr int AGGP = 4097;      // per-head stride in bufA (pad vs 4096)

// shared memory layout (float offsets)
constexpr int OFF_CTX = 0;                    // 256 rows * 65  = 16640
constexpr int OFF_W   = OFF_CTX + 256 * CTXP; // 4 mats * 64*65 = 16640
constexpr int OFF_A   = OFF_W + 4 * 64 * WP;  // 16640 (QK/AGG [h][r][t], OBUF, feats staging)
constexpr int OFF_B   = OFF_A + 16640;        // 4096  (QP / OA [r][e])
constexpr int OFF_AB  = OFF_B + 4096;         // 1024  (softmax weights [r][h][k'])
constexpr int SMEM_FLOATS = OFF_AB + 1024;    // 55040 floats = 215 KB
}

__device__ __forceinline__ float warp_sum(float v) {
#pragma unroll
    for (int o = 16; o; o >>= 1) v += __shfl_xor_sync(0xffffffffu, v, o);
    return v;
}

__global__ __launch_bounds__(THREADS, 1)
void cma_fused(const float* __restrict__ feats, const float* __restrict__ proj_w,
               const float* __restrict__ proj_b, const float* __restrict__ wq,
               const float* __restrict__ wk, const float* __restrict__ wv,
               const float* __restrict__ bq, const float* __restrict__ bk,
               const float* __restrict__ bv, const float* __restrict__ wo,
               const float* __restrict__ bo, const float* __restrict__ ng,
               const float* __restrict__ nb, const float* __restrict__ tfw,
               const float* __restrict__ fg, const float* __restrict__ fb,
               float* __restrict__ out)
{
    (void)bk;  // provably cancels in the k'-softmax (constant per (n,h))

    extern __shared__ float sm[];
    float* sctx = sm + OFF_CTX;
    float* swgt = sm + OFF_W;
    float* bufA = sm + OFF_A;
    float* bufB = sm + OFF_B;
    float* abuf = sm + OFF_AB;

    const int b    = blockIdx.x;
    const int tid  = threadIdx.x;
    const int lane = tid & 31;
    const int warp = tid >> 5;
    const int tr   = tid >> 4;   // 0..15  (row-group)
    const int tc   = tid & 15;   // 0..15  (col-group)
    const int r0   = tr * 4;
    const int c0   = tc * 4;

    // combiner weights: softmax(tfw), K=4
    float wgt[4];
    {
        float t0 = __ldg(tfw + 0), t1 = __ldg(tfw + 1), t2 = __ldg(tfw + 2), t3 = __ldg(tfw + 3);
        float tm = fmaxf(fmaxf(t0, t1), fmaxf(t2, t3));
        float e0 = __expf(t0 - tm), e1 = __expf(t1 - tm), e2 = __expf(t2 - tm), e3 = __expf(t3 - tm);
        float inv = 1.f / (e0 + e1 + e2 + e3);
        wgt[0] = e0 * inv; wgt[1] = e1 * inv; wgt[2] = e2 * inv; wgt[3] = e3 * inv;
    }

    // ================= Phase 1: proj -> sctx[(k*64+d)*CTXP + t] =================
    {
        float* sfeat = bufA;   // [c][t], 128*64
        float* spw   = swgt;   // [c*WP + d], transposed proj_w
        for (int k = 0; k < 4; k++) {
            const float4* fg4 = reinterpret_cast<const float4*>(feats + (size_t)(k * B + b) * (C * T));
            float4* sf4 = reinterpret_cast<float4*>(sfeat);
#pragma unroll
            for (int idx = tid; idx < C * T / 4; idx += THREADS) sf4[idx] = fg4[idx];
            const float* pwg = proj_w + k * (D * C);
#pragma unroll
            for (int idx = tid; idx < D * C; idx += THREADS) {
                int d = idx >> 7, c = idx & 127;
                spw[c * WP + d] = pwg[idx];
            }
            __syncthreads();

            float acc[4][4] = {};
            const float4* sfv = reinterpret_cast<const float4*>(sfeat);
#pragma unroll 8
            for (int c = 0; c < C; c++) {
                float4 f = sfv[c * 16 + tc];
#pragma unroll
                for (int j = 0; j < 4; j++) {
                    float w = spw[c * WP + r0 + j];
                    acc[j][0] += w * f.x; acc[j][1] += w * f.y;
                    acc[j][2] += w * f.z; acc[j][3] += w * f.w;
                }
            }
#pragma unroll
            for (int j = 0; j < 4; j++) {
                float pb = __ldg(proj_b + k * D + r0 + j);
                float* dst = sctx + (k * 64 + r0 + j) * CTXP + c0;
                dst[0] = acc[j][0] + pb; dst[1] = acc[j][1] + pb;
                dst[2] = acc[j][2] + pb; dst[3] = acc[j][3] + pb;
            }
            __syncthreads();
        }
    }

    // ================= Phase 2: attention for each model i =================
    for (int i = 0; i < 4; i++) {
        // stage transposed weights: s[t*WP+e] = w[e*64+t]
        {
            const float* gq = wq + i * 4096; const float* gk = wk + i * 4096;
            const float* gv = wv + i * 4096; const float* go = wo + i * 4096;
#pragma unroll
            for (int idx = tid; idx < 4096; idx += THREADS) {
                int e = idx >> 6, t = idx & 63;
                swgt[0 * 64 * WP + t * WP + e] = gq[idx];
                swgt[1 * 64 * WP + t * WP + e] = gk[idx];
                swgt[2 * 64 * WP + t * WP + e] = gv[idx];
                swgt[3 * 64 * WP + t * WP + e] = go[idx];
            }
        }
        __syncthreads();
        const float* swq_ = swgt;
        const float* swk_ = swgt + 64 * WP;
        const float* swv_ = swgt + 2 * 64 * WP;
        const float* swo_ = swgt + 3 * 64 * WP;

        int jb_[4], jq_[4];
#pragma unroll
        for (int rr = 0; rr < 4; rr++) {
            int r = r0 + rr;
            jb_[rr] = ((r >> 4) << 6) + ((r & 15) << 2);
            jq_[rr] = jb_[rr] + i;
        }

        // ---- G1: QP[r][e] = bq[e] + q_in[r] @ wq^T  -> bufB ----
        {
            float acc[4][4] = {};
#pragma unroll 8
            for (int t = 0; t < 64; t++) {
                float qv[4];
#pragma unroll
                for (int rr = 0; rr < 4; rr++) qv[rr] = sctx[jq_[rr] * CTXP + t];
#pragma unroll
                for (int j = 0; j < 4; j++) {
                    float w = swq_[t * WP + c0 + j];
                    acc[0][j] += qv[0] * w; acc[1][j] += qv[1] * w;
                    acc[2][j] += qv[2] * w; acc[3][j] += qv[3] * w;
                }
            }
#pragma unroll
            for (int rr = 0; rr < 4; rr++)
#pragma unroll
                for (int j = 0; j < 4; j++)
                    bufB[(r0 + rr) * 64 + c0 + j] = acc[rr][j] + __ldg(bq + i * 64 + c0 + j);
        }
        __syncthreads();

        // ---- G2: QK[h][r][t] = 0.25 * sum_{e in head h} QP[r][e] * wk[e][t] ----
#pragma unroll
        for (int h = 0; h < 4; h++) {
            float acc[4][4] = {};
#pragma unroll
            for (int ee = 0; ee < 16; ee++) {
                int e = h * 16 + ee;
                float qp[4];
#pragma unroll
                for (int rr = 0; rr < 4; rr++) qp[rr] = bufB[(r0 + rr) * 64 + e];
#pragma unroll
                for (int j = 0; j < 4; j++) {
                    float w = swk_[(c0 + j) * WP + e];
                    acc[0][j] += qp[0] * w; acc[1][j] += qp[1] * w;
                    acc[2][j] += qp[2] * w; acc[3][j] += qp[3] * w;
                }
            }
#pragma unroll
            for (int rr = 0; rr < 4; rr++)
#pragma unroll
                for (int j = 0; j < 4; j++)
                    bufA[h * AGGP + (r0 + rr) * 64 + c0 + j] = acc[rr][j] * 0.25f;
        }
        __syncthreads();

        // ---- G3a: scores + softmax over k' (4) -> abuf[r*16 + h*4 + kp] ----
#pragma unroll
        for (int p = 0; p < 4; p++) {
            int r   = warp * 8 + p * 2 + (lane >> 4);
            int sub = lane & 15;
            int h   = sub >> 2, kp = sub & 3;
            int j   = ((r >> 4) << 6) + ((r & 15) << 2) + kp;
            const float* qrow = bufA + h * AGGP + r * 64;
            const float* crow = sctx + j * CTXP;
            float s = 0.f;
#pragma unroll 8
            for (int t = 0; t < 64; t++) s += qrow[t] * crow[t];
            float m = fmaxf(s, __shfl_xor_sync(0xffffffffu, s, 1));
            m = fmaxf(m, __shfl_xor_sync(0xffffffffu, m, 2));
            float pe  = __expf(s - m);
            float den = pe + __shfl_xor_sync(0xffffffffu, pe, 1);
            den += __shfl_xor_sync(0xffffffffu, den, 2);
            abuf[r * 16 + sub] = pe / den;
        }
        __syncthreads();

        // ---- G3b: AGG[h][r][t] = sum_kp a[r,h,kp] * ctx[j(r,kp)][t]  (overwrites QK) ----
#pragma unroll
        for (int h = 0; h < 4; h++) {
            float acc[4][4] = {};
#pragma unroll
            for (int kp = 0; kp < 4; kp++) {
#pragma unroll
                for (int rr = 0; rr < 4; rr++) {
                    float a = abuf[(r0 + rr) * 16 + h * 4 + kp];
                    const float* crow = sctx + (jb_[rr] + kp) * CTXP + c0;
                    acc[rr][0] += a * crow[0]; acc[rr][1] += a * crow[1];
                    acc[rr][2] += a * crow[2]; acc[rr][3] += a * crow[3];
                }
            }
#pragma unroll
            for (int rr = 0; rr < 4; rr++)
#pragma unroll
                for (int j = 0; j < 4; j++)
                    bufA[h * AGGP + (r0 + rr) * 64 + c0 + j] = acc[rr][j];
        }
        __syncthreads();

        // ---- G4: OA[r][e] = bv[e] + sum_t AGG[h(e)][r][t] * wv[e][t] -> bufB ----
        {
            int h = c0 >> 4;
            float acc[4][4] = {};
#pragma unroll 8
            for (int t = 0; t < 64; t++) {
                float g[4];
#pragma unroll
                for (int rr = 0; rr < 4; rr++) g[rr] = bufA[h * AGGP + (r0 + rr) * 64 + t];
#pragma unroll
                for (int j = 0; j < 4; j++) {
                    float w = swv_[t * WP + c0 + j];
                    acc[0][j] += g[0] * w; acc[1][j] += g[1] * w;
                    acc[2][j] += g[2] * w; acc[3][j] += g[3] * w;
                }
            }
#pragma unroll
            for (int rr = 0; rr < 4; rr++)
#pragma unroll
                for (int j = 0; j < 4; j++)
                    bufB[(r0 + rr) * 64 + c0 + j] = acc[rr][j] + __ldg(bv + i * 64 + c0 + j);
        }
        __syncthreads();

        // ---- G5: O[r][e'] = bo + OA @ wo^T -> bufA[r*64+e'] ----
        {
            float acc[4][4] = {};
#pragma unroll 8
            for (int e = 0; e < 64; e++) {
                float ov[4];
#pragma unroll
                for (int rr = 0; rr < 4; rr++) ov[rr] = bufB[(r0 + rr) * 64 + e];
#pragma unroll
                for (int j = 0; j < 4; j++) {
                    float w = swo_[e * WP + c0 + j];
                    acc[0][j] += ov[0] * w; acc[1][j] += ov[1] * w;
                    acc[2][j] += ov[2] * w; acc[3][j] += ov[3] * w;
                }
            }
#pragma unroll
            for (int rr = 0; rr < 4; rr++)
#pragma unroll
                for (int j = 0; j < 4; j++)
                    bufA[(r0 + rr) * 64 + c0 + j] = acc[rr][j] + __ldg(bo + i * 64 + c0 + j);
        }
        __syncthreads();

        // ---- LN over 64 (+residual q_in), scale by wgt[i], stage into out ----
#pragma unroll
        for (int p = 0; p < 8; p++) {
            int r   = warp * 8 + p;
            int jqr = ((r >> 4) << 6) + ((r & 15) << 2) + i;
            float x0 = bufA[r * 64 + lane]      + sctx[jqr * CTXP + lane];
            float x1 = bufA[r * 64 + lane + 32] + sctx[jqr * CTXP + lane + 32];
            float mean = warp_sum(x0 + x1) * (1.f / 64.f);
            float d0 = x0 - mean, d1 = x1 - mean;
            float var = warp_sum(d0 * d0 + d1 * d1) * (1.f / 64.f);
            float rs = rsqrtf(var + EPSF);
            float* dst = out + ((size_t)b * 16384 + r * 256 + i * 64);
            dst[lane]      = (d0 * rs * __ldg(ng + i * 64 + lane)      + __ldg(nb + i * 64 + lane))      * wgt[i];
            dst[lane + 32] = (d1 * rs * __ldg(ng + i * 64 + lane + 32) + __ldg(nb + i * 64 + lane + 32)) * wgt[i];
        }
        __syncthreads();
    }

    // ================= Phase 3: final LN over K*D = 256, in-place on out =================
#pragma unroll
    for (int p = 0; p < 8; p++) {
        int r = warp * 8 + p;
        float* row = out + ((size_t)b * 16384 + r * 256);
        float x[8];
        float s = 0.f;
#pragma unroll
        for (int q = 0; q < 8; q++) { x[q] = row[lane + 32 * q]; s += x[q]; }
        float mean = warp_sum(s) * (1.f / 256.f);
        float v = 0.f;
#pragma unroll
        for (int q = 0; q < 8; q++) { x[q] -= mean; v += x[q] * x[q]; }
        float var = warp_sum(v) * (1.f / 256.f);
        float rs = rsqrtf(var + EPSF);
#pragma unroll
        for (int q = 0; q < 8; q++) {
            int jj = lane + 32 * q;
            row[jj] = x[q] * rs * __ldg(fg + jj) + __ldg(fb + jj);
        }
    }
}

extern "C" void kernel_launch(void* const* d_in, const int* in_sizes, int n_in,
                              void* d_out, int out_size) {
    (void)in_sizes; (void)n_in; (void)out_size;
    const float* feats  = (const float*)d_in[0];
    const float* proj_w = (const float*)d_in[1];
    const float* proj_b = (const float*)d_in[2];
    const float* wq     = (const float*)d_in[3];
    const float* wk     = (const float*)d_in[4];
    const float* wv     = (const float*)d_in[5];
    const float* bq     = (const float*)d_in[6];
    const float* bk     = (const float*)d_in[7];
    const float* bv     = (const float*)d_in[8];
    const float* wo     = (const float*)d_in[9];
    const float* bo     = (const float*)d_in[10];
    const float* ng     = (const float*)d_in[11];
    const float* nb     = (const float*)d_in[12];
    const float* tfw    = (const float*)d_in[13];
    const float* fg     = (const float*)d_in[14];
    const float* fb     = (const float*)d_in[15];
    float* out = (float*)d_out;

    size_t smem = SMEM_FLOATS * sizeof(float);
    cudaFuncSetAttribute(cma_fused, cudaFuncAttributeMaxDynamicSharedMemorySize, (int)smem);
    cma_fused<<<B, THREADS, smem>>>(feats, proj_w, proj_b, wq, wk, wv, bq, bk, bv,
                                    wo, bo, ng, nb, tfw, fg, fb, out);
}